// round 1
// baseline (speedup 1.0000x reference)
#include <cuda_runtime.h>

#define N_NODES 262144
#define M_EDGES 1048576
#define F_DIM   64
#define H_DIM   128
#define HEADS   3

// Scratch (static __device__ — no allocations allowed)
// g_self[h][n][0:128]  = x[n] @ gate_w1[h][0:64]  + gate_b1[h]   (bias folded)
// g_self[h][n][128:256]= x[n] @ msg_w1[h][0:64]   + msg_b1[h]
// g_nbr [h][n][0:128]  = x[n] @ gate_w1[h][64:128]
// g_nbr [h][n][128:256]= x[n] @ msg_w1[h][64:128]
__device__ float g_self[(size_t)HEADS * N_NODES * 256];
__device__ float g_nbr [(size_t)HEADS * N_NODES * 256];
__device__ float g_acc [(size_t)HEADS * N_NODES * 128];  // sum_e attn*leaky(msg hidden)
__device__ float g_sattn[(size_t)HEADS * N_NODES];       // sum_e attn
__device__ int   g_rowptr[N_NODES + 1];

__device__ __forceinline__ float lk(float x) { return x >= 0.f ? x : 0.01f * x; }

// ---------------------------------------------------------------------------
// K1: node precompute GEMMs. C[N x 128] = X[N x 64] @ W[64 x 128] (+bias)
// grid.z in 0..11 selects (head, {self-gate, self-msg, nbr-gate, nbr-msg})
// ---------------------------------------------------------------------------
__global__ void node_gemm_kernel(const float* __restrict__ X,
                                 const float* __restrict__ gate_w1,
                                 const float* __restrict__ gate_b1,
                                 const float* __restrict__ msg_w1,
                                 const float* __restrict__ msg_b1)
{
    const int z = blockIdx.z;
    const int h = z >> 2;
    const int kind = z & 3;
    const float* W;
    const float* bias = nullptr;
    float* dst;
    const size_t base = (size_t)h * N_NODES * 256;
    if (kind == 0)      { W = gate_w1 + (size_t)h*128*128;          bias = gate_b1 + h*128; dst = g_self + base; }
    else if (kind == 1) { W = msg_w1  + (size_t)h*128*128;          bias = msg_b1  + h*128; dst = g_self + base + 128; }
    else if (kind == 2) { W = gate_w1 + (size_t)h*128*128 + 64*128;                         dst = g_nbr  + base; }
    else                { W = msg_w1  + (size_t)h*128*128 + 64*128;                         dst = g_nbr  + base + 128; }

    __shared__ float Xs[128][36];   // 128 nodes x 32 k (+4 pad)
    __shared__ float Ws[32][128];   // 32 k x 128 cols

    const int tid = threadIdx.x;         // 256 threads
    const int tx = tid & 15;             // 16 col groups of 8
    const int ty = tid >> 4;             // 16 row groups of 8
    const int n0 = blockIdx.x * 128;

    float acc[8][8];
    #pragma unroll
    for (int i = 0; i < 8; i++)
        #pragma unroll
        for (int j = 0; j < 8; j++) acc[i][j] = 0.f;

    #pragma unroll
    for (int kt = 0; kt < 2; kt++) {
        const int k0 = kt * 32;
        // X tile: 128 x 32
        {
            const int node = tid >> 1;
            const int seg = (tid & 1) * 16;
            const float4* src = (const float4*)(X + (size_t)(n0 + node) * 64 + k0 + seg);
            float4* d = (float4*)&Xs[node][seg];
            d[0] = src[0]; d[1] = src[1]; d[2] = src[2]; d[3] = src[3];
        }
        // W tile: 32 x 128
        #pragma unroll
        for (int it = 0; it < 4; it++) {
            const int f4  = tid + it * 256;       // 0..1023 float4s
            const int row = f4 >> 5;              // 32 float4 per row
            const int c4  = f4 & 31;
            ((float4*)&Ws[row][c4 * 4])[0] = ((const float4*)(W + (size_t)(k0 + row) * 128))[c4];
        }
        __syncthreads();

        #pragma unroll
        for (int k = 0; k < 32; k++) {
            float a[8], b[8];
            #pragma unroll
            for (int i = 0; i < 8; i++) a[i] = Xs[ty * 8 + i][k];
            float4 bv0 = *(const float4*)&Ws[k][tx * 8];
            float4 bv1 = *(const float4*)&Ws[k][tx * 8 + 4];
            b[0]=bv0.x; b[1]=bv0.y; b[2]=bv0.z; b[3]=bv0.w;
            b[4]=bv1.x; b[5]=bv1.y; b[6]=bv1.z; b[7]=bv1.w;
            #pragma unroll
            for (int i = 0; i < 8; i++)
                #pragma unroll
                for (int j = 0; j < 8; j++) acc[i][j] += a[i] * b[j];
        }
        __syncthreads();
    }

    float bv[8];
    #pragma unroll
    for (int j = 0; j < 8; j++) bv[j] = bias ? bias[tx * 8 + j] : 0.f;

    #pragma unroll
    for (int i = 0; i < 8; i++) {
        const size_t row = (size_t)(n0 + ty * 8 + i) * 256;
        float4 o0 = make_float4(acc[i][0]+bv[0], acc[i][1]+bv[1], acc[i][2]+bv[2], acc[i][3]+bv[3]);
        float4 o1 = make_float4(acc[i][4]+bv[4], acc[i][5]+bv[5], acc[i][6]+bv[6], acc[i][7]+bv[7]);
        *(float4*)(dst + row + tx * 8)     = o0;
        *(float4*)(dst + row + tx * 8 + 4) = o1;
    }
}

// ---------------------------------------------------------------------------
// CSR row pointers from sorted self_fea_idx
// ---------------------------------------------------------------------------
__global__ void rowptr_kernel(const int* __restrict__ self_idx)
{
    const int e = blockIdx.x * blockDim.x + threadIdx.x;
    if (e >= M_EDGES) return;
    const int s = self_idx[e];
    const int prev = (e == 0) ? -1 : self_idx[e - 1];
    for (int n = prev + 1; n <= s; n++) g_rowptr[n] = e;
    if (e == M_EDGES - 1)
        for (int n = s + 1; n <= N_NODES; n++) g_rowptr[n] = M_EDGES;
}

// ---------------------------------------------------------------------------
// K2: fused per-(node,head) softmax + weighted hidden accumulation.
// One warp per (node, head). Single pass, no atomics.
//   g_e   = w2 . leaky(self_g + nbr_g)  + b2
//   e_e   = w_nbr * exp(g_e)
//   num_k = sum_e e_e * leaky(self_m + nbr_m)_k ;  denom = sum_e e_e
//   acc   = num / (denom + 1e-10) ;  sattn = denom / (denom + 1e-10)
// (softmax is shift-invariant; g is O(1) so no max pass needed)
// ---------------------------------------------------------------------------
__global__ void edge_kernel(const int* __restrict__ nbr_idx,
                            const float* __restrict__ elem_weights,
                            const float* __restrict__ gate_w2,
                            const float* __restrict__ gate_b2)
{
    const int wid = blockIdx.x * 8 + (threadIdx.x >> 5);
    const int lane = threadIdx.x & 31;
    if (wid >= N_NODES * HEADS) return;
    const int n = wid / HEADS;
    const int h = wid - n * HEADS;

    const size_t sbase = ((size_t)h * N_NODES + n) * 256;
    const float4 sg = *(const float4*)(g_self + sbase + lane * 4);
    const float4 sm = *(const float4*)(g_self + sbase + 128 + lane * 4);
    const float4 w2 = *(const float4*)(gate_w2 + h * 128 + lane * 4);
    const float b2 = gate_b2[h];

    const int e0 = g_rowptr[n];
    const int e1 = g_rowptr[n + 1];

    float nx = 0.f, ny = 0.f, nz = 0.f, nw = 0.f;
    float denom = 0.f;

    for (int e = e0; e < e1; e++) {
        const int j = __ldg(&nbr_idx[e]);
        const float w = __ldg(&elem_weights[j]);
        const size_t nb = ((size_t)h * N_NODES + j) * 256;
        const float4 ng = *(const float4*)(g_nbr + nb + lane * 4);
        const float4 nm = *(const float4*)(g_nbr + nb + 128 + lane * 4);

        // gate
        float p = lk(sg.x + ng.x) * w2.x + lk(sg.y + ng.y) * w2.y
                + lk(sg.z + ng.z) * w2.z + lk(sg.w + ng.w) * w2.w;
        p += __shfl_xor_sync(0xffffffffu, p, 16);
        p += __shfl_xor_sync(0xffffffffu, p, 8);
        p += __shfl_xor_sync(0xffffffffu, p, 4);
        p += __shfl_xor_sync(0xffffffffu, p, 2);
        p += __shfl_xor_sync(0xffffffffu, p, 1);
        const float ev = w * __expf(p + b2);
        denom += ev;

        nx += ev * lk(sm.x + nm.x);
        ny += ev * lk(sm.y + nm.y);
        nz += ev * lk(sm.z + nm.z);
        nw += ev * lk(sm.w + nm.w);
    }

    const float inv = 1.f / (denom + 1e-10f);
    const size_t abase = ((size_t)h * N_NODES + n) * 128;
    *(float4*)(g_acc + abase + lane * 4) = make_float4(nx * inv, ny * inv, nz * inv, nw * inv);
    if (lane == 0) g_sattn[(size_t)h * N_NODES + n] = denom * inv;
}

// ---------------------------------------------------------------------------
// K3: out[n][f] = x[n][f] + (1/3) * sum_h ( acc[h][n] @ msg_w2[h] + sattn[h][n]*msg_b2[h][f] )
// GEMM: C[N x 64] = A[N x 384] @ W[384 x 64]
// ---------------------------------------------------------------------------
__global__ void out_gemm_kernel(const float* __restrict__ msg_w2,
                                const float* __restrict__ msg_b2,
                                const float* __restrict__ X,
                                float* __restrict__ out)
{
    __shared__ float As[128][36];
    __shared__ float Ws[32][64];

    const int tid = threadIdx.x;   // 256
    const int tx = tid & 15;       // 16 col groups of 4
    const int ty = tid >> 4;       // 16 row groups of 8
    const int n0 = blockIdx.x * 128;

    float acc[8][4];
    #pragma unroll
    for (int i = 0; i < 8; i++)
        #pragma unroll
        for (int j = 0; j < 4; j++) acc[i][j] = 0.f;

    for (int h = 0; h < HEADS; h++) {
        #pragma unroll
        for (int kt = 0; kt < 4; kt++) {
            const int k0 = kt * 32;
            {
                const int node = tid >> 1;
                const int seg = (tid & 1) * 16;
                const float4* src = (const float4*)(g_acc + ((size_t)h * N_NODES + n0 + node) * 128 + k0 + seg);
                float4* d = (float4*)&As[node][seg];
                d[0] = src[0]; d[1] = src[1]; d[2] = src[2]; d[3] = src[3];
            }
            #pragma unroll
            for (int it = 0; it < 2; it++) {
                const int f4  = tid + it * 256;   // 0..511
                const int row = f4 >> 4;          // 16 float4 per 64-col row
                const int c4  = f4 & 15;
                ((float4*)&Ws[row][c4 * 4])[0] =
                    ((const float4*)(msg_w2 + ((size_t)h * 128 + k0 + row) * 64))[c4];
            }
            __syncthreads();

            #pragma unroll
            for (int k = 0; k < 32; k++) {
                const float4 bv = *(const float4*)&Ws[k][tx * 4];
                #pragma unroll
                for (int i = 0; i < 8; i++) {
                    const float a = As[ty * 8 + i][k];
                    acc[i][0] += a * bv.x;
                    acc[i][1] += a * bv.y;
                    acc[i][2] += a * bv.z;
                    acc[i][3] += a * bv.w;
                }
            }
            __syncthreads();
        }
    }

    const float inv3 = 1.f / 3.f;
    #pragma unroll
    for (int i = 0; i < 8; i++) {
        const int n = n0 + ty * 8 + i;
        const float s0 = g_sattn[(size_t)0 * N_NODES + n];
        const float s1 = g_sattn[(size_t)1 * N_NODES + n];
        const float s2 = g_sattn[(size_t)2 * N_NODES + n];
        const float4 xv = *(const float4*)(X + (size_t)n * 64 + tx * 4);
        float o[4];
        #pragma unroll
        for (int j = 0; j < 4; j++) {
            const int f = tx * 4 + j;
            const float bterm = s0 * msg_b2[0 * 64 + f] + s1 * msg_b2[64 + f] + s2 * msg_b2[128 + f];
            o[j] = inv3 * (acc[i][j] + bterm);
        }
        float4 ov = make_float4(o[0] + xv.x, o[1] + xv.y, o[2] + xv.z, o[3] + xv.w);
        *(float4*)(out + (size_t)n * 64 + tx * 4) = ov;
    }
}

// ---------------------------------------------------------------------------
extern "C" void kernel_launch(void* const* d_in, const int* in_sizes, int n_in,
                              void* d_out, int out_size)
{
    const float* elem_weights = (const float*)d_in[0];
    const float* x            = (const float*)d_in[1];
    const int*   self_idx     = (const int*)  d_in[2];
    const int*   nbr_idx      = (const int*)  d_in[3];
    const float* gate_w1      = (const float*)d_in[4];
    const float* gate_b1      = (const float*)d_in[5];
    const float* gate_w2      = (const float*)d_in[6];
    const float* gate_b2      = (const float*)d_in[7];
    const float* msg_w1       = (const float*)d_in[8];
    const float* msg_b1       = (const float*)d_in[9];
    const float* msg_w2       = (const float*)d_in[10];
    const float* msg_b2       = (const float*)d_in[11];
    float* out = (float*)d_out;

    dim3 g1(N_NODES / 128, 1, 12);
    node_gemm_kernel<<<g1, 256>>>(x, gate_w1, gate_b1, msg_w1, msg_b1);
    rowptr_kernel<<<M_EDGES / 256, 256>>>(self_idx);
    edge_kernel<<<(N_NODES * HEADS) / 8, 256>>>(nbr_idx, elem_weights, gate_w2, gate_b2);
    out_gemm_kernel<<<N_NODES / 128, 256>>>(msg_w2, msg_b2, x, out);
}

// round 3
// speedup vs baseline: 1.4666x; 1.4666x over previous
#include <cuda_runtime.h>
#include <cuda_fp16.h>
#include <cstdint>

#define N_NODES 262144
#define M_EDGES 1048576
#define F_DIM   64
#define H_DIM   128
#define HEADS   3

// Scratch (static __device__ — no allocations allowed)
// Node-major fp16 tables: for node n, head h:
//   g_self_h[(n*3+h)*256 + 0:128]   = x[n] @ gate_w1[h][0:64]  + gate_b1[h]
//   g_self_h[(n*3+h)*256 + 128:256] = x[n] @ msg_w1[h][0:64]   + msg_b1[h]
//   g_nbr_h [(n*3+h)*256 + 0:128]   = x[n] @ gate_w1[h][64:128]
//   g_nbr_h [(n*3+h)*256 + 128:256] = x[n] @ msg_w1[h][64:128]
__device__ __half g_self_h[(size_t)HEADS * N_NODES * 256];
__device__ __half g_nbr_h [(size_t)HEADS * N_NODES * 256];
__device__ float  g_acc [(size_t)HEADS * N_NODES * 128];  // sum_e attn*leaky(msg hidden)
__device__ float  g_sattn[(size_t)HEADS * N_NODES];       // sum_e attn
__device__ int    g_rowptr[N_NODES + 1];

__device__ __forceinline__ float lk(float x) { return x >= 0.f ? x : 0.01f * x; }

__device__ __forceinline__ uint32_t f2tf(float f) {
    uint32_t u;
    asm("cvt.rna.tf32.f32 %0, %1;" : "=r"(u) : "f"(f));
    return u;
}

__device__ __forceinline__ void mma_tf32(float* c, const uint32_t* a, const uint32_t* b) {
    asm volatile(
        "mma.sync.aligned.m16n8k8.row.col.f32.tf32.tf32.f32 "
        "{%0,%1,%2,%3},{%4,%5,%6,%7},{%8,%9},{%0,%1,%2,%3};"
        : "+f"(c[0]), "+f"(c[1]), "+f"(c[2]), "+f"(c[3])
        : "r"(a[0]), "r"(a[1]), "r"(a[2]), "r"(a[3]), "r"(b[0]), "r"(b[1]));
}

// ---------------------------------------------------------------------------
// K1: node precompute GEMMs via tf32 tensor cores.
// C[128 x 128] tile = X[128 x 64] @ W[64 x 128] (+bias), output fp16.
// grid = (N/128, 1, 12); z selects (head, {self-gate, self-msg, nbr-gate, nbr-msg})
// ---------------------------------------------------------------------------
__global__ void node_gemm_kernel(const float* __restrict__ X,
                                 const float* __restrict__ gate_w1,
                                 const float* __restrict__ gate_b1,
                                 const float* __restrict__ msg_w1,
                                 const float* __restrict__ msg_b1)
{
    const int z = blockIdx.z;
    const int h = z >> 2;
    const int kind = z & 3;
    const float* W;
    const float* bias = nullptr;
    if (kind == 0)      { W = gate_w1 + (size_t)h*128*128;          bias = gate_b1 + h*128; }
    else if (kind == 1) { W = msg_w1  + (size_t)h*128*128;          bias = msg_b1  + h*128; }
    else if (kind == 2) { W = gate_w1 + (size_t)h*128*128 + 64*128; }
    else                { W = msg_w1  + (size_t)h*128*128 + 64*128; }
    __half* table = (kind < 2) ? g_self_h : g_nbr_h;
    const int off = (kind & 1) * 128;

    __shared__ uint32_t As[128][36];   // 128 nodes x 32 k (tf32 bits, pad 36)
    __shared__ uint32_t Bs[32][136];   // 32 k x 128 cols (tf32 bits, pad 136)

    const int tid  = threadIdx.x;      // 256 threads, 8 warps
    const int wid  = tid >> 5;
    const int lane = tid & 31;
    const int gid  = lane >> 2;        // 0..7
    const int tig  = lane & 3;         // 0..3
    const int warp_m = wid & 3;        // 4 warps over 128 rows (32 each)
    const int warp_n = wid >> 2;       // 2 warps over 128 cols (64 each)
    const int n0 = blockIdx.x * 128;
    const int cb_w = warp_n * 64;

    float acc[2][8][4];
    #pragma unroll
    for (int m = 0; m < 2; m++)
        #pragma unroll
        for (int n = 0; n < 8; n++)
            #pragma unroll
            for (int j = 0; j < 4; j++) acc[m][n][j] = 0.f;

    #pragma unroll
    for (int kt = 0; kt < 2; kt++) {
        // Fill A chunk: 128 nodes x 32 k
        #pragma unroll
        for (int it = 0; it < 4; it++) {
            const int f4 = tid + it * 256;          // 0..1023
            const int node = f4 >> 3;
            const int c4 = (f4 & 7) * 4;
            float4 v = *(const float4*)(X + (size_t)(n0 + node) * 64 + kt * 32 + c4);
            As[node][c4 + 0] = f2tf(v.x);
            As[node][c4 + 1] = f2tf(v.y);
            As[node][c4 + 2] = f2tf(v.z);
            As[node][c4 + 3] = f2tf(v.w);
        }
        // Fill B chunk: 32 k x 128 cols
        #pragma unroll
        for (int it = 0; it < 4; it++) {
            const int f4 = tid + it * 256;          // 0..1023
            const int row = f4 >> 5;
            const int c4 = (f4 & 31) * 4;
            float4 v = *(const float4*)(W + (size_t)(kt * 32 + row) * 128 + c4);
            Bs[row][c4 + 0] = f2tf(v.x);
            Bs[row][c4 + 1] = f2tf(v.y);
            Bs[row][c4 + 2] = f2tf(v.z);
            Bs[row][c4 + 3] = f2tf(v.w);
        }
        __syncthreads();

        #pragma unroll
        for (int ks = 0; ks < 4; ks++) {
            const int k0 = ks * 8;
            uint32_t a[2][4];
            #pragma unroll
            for (int m = 0; m < 2; m++) {
                const int rb = warp_m * 32 + m * 16;
                a[m][0] = As[rb + gid    ][k0 + tig    ];
                a[m][1] = As[rb + gid + 8][k0 + tig    ];
                a[m][2] = As[rb + gid    ][k0 + tig + 4];
                a[m][3] = As[rb + gid + 8][k0 + tig + 4];
            }
            uint32_t b[8][2];
            #pragma unroll
            for (int n = 0; n < 8; n++) {
                const int cb = cb_w + n * 8 + gid;
                b[n][0] = Bs[k0 + tig    ][cb];
                b[n][1] = Bs[k0 + tig + 4][cb];
            }
            #pragma unroll
            for (int m = 0; m < 2; m++)
                #pragma unroll
                for (int n = 0; n < 8; n++)
                    mma_tf32(acc[m][n], a[m], b[n]);
        }
        __syncthreads();
    }

    // Epilogue: add bias, convert fp16, store node-major
    #pragma unroll
    for (int m = 0; m < 2; m++) {
        #pragma unroll
        for (int hr = 0; hr < 2; hr++) {
            const int row = n0 + warp_m * 32 + m * 16 + gid + hr * 8;
            __half* dst = table + ((size_t)row * 3 + h) * 256 + off;
            #pragma unroll
            for (int n = 0; n < 8; n++) {
                const int col = cb_w + n * 8 + 2 * tig;
                float v0 = acc[m][n][hr * 2 + 0];
                float v1 = acc[m][n][hr * 2 + 1];
                if (bias) { v0 += bias[col]; v1 += bias[col + 1]; }
                *(__half2*)(dst + col) = __floats2half2_rn(v0, v1);
            }
        }
    }
}

// ---------------------------------------------------------------------------
// CSR row pointers from sorted self_fea_idx
// ---------------------------------------------------------------------------
__global__ void rowptr_kernel(const int* __restrict__ self_idx)
{
    const int e = blockIdx.x * blockDim.x + threadIdx.x;
    if (e >= M_EDGES) return;
    const int s = self_idx[e];
    const int prev = (e == 0) ? -1 : self_idx[e - 1];
    for (int n = prev + 1; n <= s; n++) g_rowptr[n] = e;
    if (e == M_EDGES - 1)
        for (int n = s + 1; n <= N_NODES; n++) g_rowptr[n] = M_EDGES;
}

// ---------------------------------------------------------------------------
// K2: fused per-(node,head) softmax + weighted hidden accumulation.
// One warp per (node, head). Single pass, no atomics, fp16 table reads.
// ---------------------------------------------------------------------------
__global__ void edge_kernel(const int* __restrict__ nbr_idx,
                            const float* __restrict__ elem_weights,
                            const float* __restrict__ gate_w2,
                            const float* __restrict__ gate_b2)
{
    const int wid = blockIdx.x * 8 + (threadIdx.x >> 5);
    const int lane = threadIdx.x & 31;
    if (wid >= N_NODES * HEADS) return;
    const int n = wid / HEADS;
    const int h = wid - n * HEADS;

    const size_t sbase = ((size_t)n * 3 + h) * 256;
    uint2 sgu = *(const uint2*)(g_self_h + sbase + lane * 4);
    uint2 smu = *(const uint2*)(g_self_h + sbase + 128 + lane * 4);
    const float2 sg0 = __half22float2(*(__half2*)&sgu.x);
    const float2 sg1 = __half22float2(*(__half2*)&sgu.y);
    const float2 sm0 = __half22float2(*(__half2*)&smu.x);
    const float2 sm1 = __half22float2(*(__half2*)&smu.y);
    const float4 w2 = *(const float4*)(gate_w2 + h * 128 + lane * 4);
    const float b2 = gate_b2[h];

    const int e0 = g_rowptr[n];
    const int e1 = g_rowptr[n + 1];

    float nx = 0.f, ny = 0.f, nz = 0.f, nw = 0.f;
    float denom = 0.f;

    for (int e = e0; e < e1; e++) {
        const int j = __ldg(&nbr_idx[e]);
        const float w = __ldg(&elem_weights[j]);
        const size_t nb = ((size_t)j * 3 + h) * 256;
        uint2 ngu = *(const uint2*)(g_nbr_h + nb + lane * 4);
        uint2 nmu = *(const uint2*)(g_nbr_h + nb + 128 + lane * 4);
        const float2 ng0 = __half22float2(*(__half2*)&ngu.x);
        const float2 ng1 = __half22float2(*(__half2*)&ngu.y);
        const float2 nm0 = __half22float2(*(__half2*)&nmu.x);
        const float2 nm1 = __half22float2(*(__half2*)&nmu.y);

        // gate logit partial dot
        float p = lk(sg0.x + ng0.x) * w2.x + lk(sg0.y + ng0.y) * w2.y
                + lk(sg1.x + ng1.x) * w2.z + lk(sg1.y + ng1.y) * w2.w;
        p += __shfl_xor_sync(0xffffffffu, p, 16);
        p += __shfl_xor_sync(0xffffffffu, p, 8);
        p += __shfl_xor_sync(0xffffffffu, p, 4);
        p += __shfl_xor_sync(0xffffffffu, p, 2);
        p += __shfl_xor_sync(0xffffffffu, p, 1);
        const float ev = w * __expf(p + b2);
        denom += ev;

        nx += ev * lk(sm0.x + nm0.x);
        ny += ev * lk(sm0.y + nm0.y);
        nz += ev * lk(sm1.x + nm1.x);
        nw += ev * lk(sm1.y + nm1.y);
    }

    const float inv = 1.f / (denom + 1e-10f);
    const size_t abase = ((size_t)h * N_NODES + n) * 128;
    *(float4*)(g_acc + abase + lane * 4) = make_float4(nx * inv, ny * inv, nz * inv, nw * inv);
    if (lane == 0) g_sattn[(size_t)h * N_NODES + n] = denom * inv;
}

// ---------------------------------------------------------------------------
// K3: out[n][f] = x[n][f] + (1/3) * sum_h ( acc[h][n] @ msg_w2[h] + sattn[h][n]*msg_b2[h][f] )
// GEMM: C[N x 64] = A[N x 384] @ W[384 x 64]
// ---------------------------------------------------------------------------
__global__ void out_gemm_kernel(const float* __restrict__ msg_w2,
                                const float* __restrict__ msg_b2,
                                const float* __restrict__ X,
                                float* __restrict__ out)
{
    __shared__ float As[128][36];
    __shared__ float Ws[32][64];

    const int tid = threadIdx.x;   // 256
    const int tx = tid & 15;       // 16 col groups of 4
    const int ty = tid >> 4;       // 16 row groups of 8
    const int n0 = blockIdx.x * 128;

    float acc[8][4];
    #pragma unroll
    for (int i = 0; i < 8; i++)
        #pragma unroll
        for (int j = 0; j < 4; j++) acc[i][j] = 0.f;

    for (int h = 0; h < HEADS; h++) {
        #pragma unroll
        for (int kt = 0; kt < 4; kt++) {
            const int k0 = kt * 32;
            {
                const int node = tid >> 1;
                const int seg = (tid & 1) * 16;
                const float4* src = (const float4*)(g_acc + ((size_t)h * N_NODES + n0 + node) * 128 + k0 + seg);
                float4* d = (float4*)&As[node][seg];
                d[0] = src[0]; d[1] = src[1]; d[2] = src[2]; d[3] = src[3];
            }
            #pragma unroll
            for (int it = 0; it < 2; it++) {
                const int f4  = tid + it * 256;   // 0..511
                const int row = f4 >> 4;          // 16 float4 per 64-col row
                const int c4  = f4 & 15;
                ((float4*)&Ws[row][c4 * 4])[0] =
                    ((const float4*)(msg_w2 + ((size_t)h * 128 + k0 + row) * 64))[c4];
            }
            __syncthreads();

            #pragma unroll
            for (int k = 0; k < 32; k++) {
                const float4 bv = *(const float4*)&Ws[k][tx * 4];
                #pragma unroll
                for (int i = 0; i < 8; i++) {
                    const float a = As[ty * 8 + i][k];
                    acc[i][0] += a * bv.x;
                    acc[i][1] += a * bv.y;
                    acc[i][2] += a * bv.z;
                    acc[i][3] += a * bv.w;
                }
            }
            __syncthreads();
        }
    }

    const float inv3 = 1.f / 3.f;
    #pragma unroll
    for (int i = 0; i < 8; i++) {
        const int n = n0 + ty * 8 + i;
        const float s0 = g_sattn[(size_t)0 * N_NODES + n];
        const float s1 = g_sattn[(size_t)1 * N_NODES + n];
        const float s2 = g_sattn[(size_t)2 * N_NODES + n];
        const float4 xv = *(const float4*)(X + (size_t)n * 64 + tx * 4);
        float o[4];
        #pragma unroll
        for (int j = 0; j < 4; j++) {
            const int f = tx * 4 + j;
            const float bterm = s0 * msg_b2[0 * 64 + f] + s1 * msg_b2[64 + f] + s2 * msg_b2[128 + f];
            o[j] = inv3 * (acc[i][j] + bterm);
        }
        float4 ov = make_float4(o[0] + xv.x, o[1] + xv.y, o[2] + xv.z, o[3] + xv.w);
        *(float4*)(out + (size_t)n * 64 + tx * 4) = ov;
    }
}

// ---------------------------------------------------------------------------
extern "C" void kernel_launch(void* const* d_in, const int* in_sizes, int n_in,
                              void* d_out, int out_size)
{
    const float* elem_weights = (const float*)d_in[0];
    const float* x            = (const float*)d_in[1];
    const int*   self_idx     = (const int*)  d_in[2];
    const int*   nbr_idx      = (const int*)  d_in[3];
    const float* gate_w1      = (const float*)d_in[4];
    const float* gate_b1      = (const float*)d_in[5];
    const float* gate_w2      = (const float*)d_in[6];
    const float* gate_b2      = (const float*)d_in[7];
    const float* msg_w1       = (const float*)d_in[8];
    const float* msg_b1       = (const float*)d_in[9];
    const float* msg_w2       = (const float*)d_in[10];
    const float* msg_b2       = (const float*)d_in[11];
    float* out = (float*)d_out;

    dim3 g1(N_NODES / 128, 1, 12);
    node_gemm_kernel<<<g1, 256>>>(x, gate_w1, gate_b1, msg_w1, msg_b1);
    rowptr_kernel<<<M_EDGES / 256, 256>>>(self_idx);
    edge_kernel<<<(N_NODES * HEADS) / 8, 256>>>(nbr_idx, elem_weights, gate_w2, gate_b2);
    out_gemm_kernel<<<N_NODES / 128, 256>>>(msg_w2, msg_b2, x, out);
}